// round 7
// baseline (speedup 1.0000x reference)
#include <cuda_runtime.h>
#include <cstdint>

// out[n] = realism(std(chunks[n])) + 0.15 + 0.2*cos(chunks[n,:10,:], prev[118:,:])
// chunks: [4096,128,64] f32 (8192 floats / 2048 float4 per chunk)
// prev:   [128,64] f32 (ctx = last 10 rows = 640 floats = 160 float4)
// out:    [4096] f32
//
// Warp-autonomous: one warp per chunk. No __syncthreads, no shared memory.
// Lane l of the warp reads float4 indices (32*i + l), i = 0..63 (512B/warp/load).

__device__ __forceinline__ void fma2(unsigned long long& acc, unsigned long long a, unsigned long long b) {
    asm("fma.rn.f32x2 %0, %1, %2, %0;" : "+l"(acc) : "l"(a), "l"(b));
}
__device__ __forceinline__ void add2(unsigned long long& acc, unsigned long long a) {
    asm("add.rn.f32x2 %0, %0, %1;" : "+l"(acc) : "l"(a));
}
__device__ __forceinline__ float hsum2(unsigned long long v) {
    float lo, hi;
    asm("mov.b64 {%0,%1}, %2;" : "=f"(lo), "=f"(hi) : "l"(v));
    return lo + hi;
}

__global__ __launch_bounds__(128) void chunk_ranker_kernel(
    const float* __restrict__ chunks,
    const float* __restrict__ prev,
    float* __restrict__ out)
{
    const int lane = threadIdx.x & 31;
    const int c = blockIdx.x * 4 + (threadIdx.x >> 5);   // chunk id = global warp id

    const ulonglong2* cb = reinterpret_cast<const ulonglong2*>(chunks + (size_t)c * 8192);
    const ulonglong2* ctx = reinterpret_cast<const ulonglong2*>(prev + 118 * 64);

    unsigned long long sum2 = 0ull, sqa = 0ull, sqb = 0ull;
    unsigned long long dot2 = 0ull, ssq2 = 0ull, csq2 = 0ull;

    // First 8 iterations (float4 idx 0..255). Prefix = idx < 160 -> i < 5 (static).
    #pragma unroll
    for (int i = 0; i < 8; i++) {
        ulonglong2 v = __ldg(&cb[i * 32 + lane]);
        add2(sum2, v.x); add2(sum2, v.y);
        fma2(sqa, v.x, v.x); fma2(sqb, v.y, v.y);
        if (i < 5) {
            ulonglong2 cc = __ldg(&ctx[i * 32 + lane]);
            fma2(dot2, v.x, cc.x); fma2(dot2, v.y, cc.y);
            fma2(ssq2, v.x, v.x);  fma2(ssq2, v.y, v.y);
            fma2(csq2, cc.x, cc.x); fma2(csq2, cc.y, cc.y);
        }
    }
    // Remaining 56 iterations (idx 256..2047), batched 8 deep for MLP.
    #pragma unroll 8
    for (int i = 8; i < 64; i++) {
        ulonglong2 v = __ldg(&cb[i * 32 + lane]);
        add2(sum2, v.x); add2(sum2, v.y);
        fma2(sqa, v.x, v.x); fma2(sqb, v.y, v.y);
    }

    float sum = hsum2(sum2);
    float sq  = hsum2(sqa) + hsum2(sqb);
    float dot = hsum2(dot2);
    float ssq = hsum2(ssq2);
    float csq = hsum2(csq2);

    #pragma unroll
    for (int off = 16; off > 0; off >>= 1) {
        sum += __shfl_down_sync(0xffffffffu, sum, off);
        sq  += __shfl_down_sync(0xffffffffu, sq,  off);
        dot += __shfl_down_sync(0xffffffffu, dot, off);
        ssq += __shfl_down_sync(0xffffffffu, ssq, off);
        csq += __shfl_down_sync(0xffffffffu, csq, off);
    }

    if (lane == 0) {
        const float M = 8192.0f;
        float var = (sq - sum * sum / M) / (M - 1.0f);
        float sd = sqrtf(fmaxf(var, 0.0f));

        float realism;
        if (sd < 0.01f)      realism = sd * 10.0f;
        else if (sd > 0.5f)  realism = 0.5f / sd;
        else                 realism = 1.0f - fabsf(sd - 0.1f);

        float denom = fmaxf(sqrtf(ssq) * sqrtf(csq), 1e-8f);
        float boundary = dot / denom;

        out[c] = realism + 0.3f * 0.5f + 0.2f * boundary;
    }
}

extern "C" void kernel_launch(void* const* d_in, const int* in_sizes, int n_in,
                              void* d_out, int out_size)
{
    const float* chunks = (const float*)d_in[0];   // [4096,128,64] f32
    // d_in[1] = regime_probs [9] — unused (constant 0.5 consistency)
    const float* prev = (const float*)d_in[2];     // [128,64] f32
    float* out = (float*)d_out;                    // [4096] f32

    const int n_chunks = in_sizes[0] / (128 * 64); // 4096
    chunk_ranker_kernel<<<n_chunks / 4, 128>>>(chunks, prev, out);
}

// round 8
// speedup vs baseline: 1.0587x; 1.0587x over previous
#include <cuda_runtime.h>
#include <cstdint>

// out[n] = realism(std(chunks[n])) + 0.15 + 0.2*cos(chunks[n,:10,:], prev[118:,:])
// chunks: [4096,128,64] f32 (32KB/chunk), prev: [128,64] f32, out: [4096] f32
//
// Hybrid: per CTA, TMA pulls the second 16KB of the chunk into SMEM while the
// threads LDG the first 16KB from global. Two concurrent request paths
// (TMA engine + LSU), 8 CTAs/SM (64 warps/SM) via launch_bounds(256,8).

__device__ __forceinline__ uint32_t smem_u32(const void* p) {
    uint32_t a;
    asm("{ .reg .u64 t; cvta.to.shared.u64 t, %1; cvt.u32.u64 %0, t; }" : "=r"(a) : "l"(p));
    return a;
}
__device__ __forceinline__ void fma2(unsigned long long& acc, unsigned long long a, unsigned long long b) {
    asm("fma.rn.f32x2 %0, %1, %2, %0;" : "+l"(acc) : "l"(a), "l"(b));
}
__device__ __forceinline__ void add2(unsigned long long& acc, unsigned long long a) {
    asm("add.rn.f32x2 %0, %0, %1;" : "+l"(acc) : "l"(a));
}
__device__ __forceinline__ float hsum2(unsigned long long v) {
    float lo, hi;
    asm("mov.b64 {%0,%1}, %2;" : "=f"(lo), "=f"(hi) : "l"(v));
    return lo + hi;
}

__global__ __launch_bounds__(256, 8) void chunk_ranker_kernel(
    const float* __restrict__ chunks,
    const float* __restrict__ prev,
    float* __restrict__ out)
{
    __shared__ __align__(128) float tile[4096];      // 16 KB (second half of chunk)
    __shared__ __align__(8) unsigned long long mbar;
    __shared__ float red[8][5];

    const int n = blockIdx.x;
    const int t = threadIdx.x;
    const uint32_t mbar_a = smem_u32(&mbar);
    const uint32_t tile_a = smem_u32(tile);

    if (t == 0) {
        asm volatile("mbarrier.init.shared.b64 [%0], 1;" :: "r"(mbar_a) : "memory");
    }
    __syncthreads();

    const float* src = chunks + (size_t)n * 8192;

    // Kick the TMA for floats [4096, 8192) immediately.
    if (t == 0) {
        asm volatile("mbarrier.arrive.expect_tx.shared.b64 _, [%0], %1;"
                     :: "r"(mbar_a), "r"(16384u) : "memory");
        asm volatile("cp.async.bulk.shared::cta.global.mbarrier::complete_tx::bytes "
                     "[%0], [%1], %2, [%3];"
                     :: "r"(tile_a), "l"(src + 4096), "r"(16384u), "r"(mbar_a) : "memory");
    }

    // Meanwhile LDG the first 16KB (1024 float4): thread t -> idx t + 256*i.
    const ulonglong2* cb = reinterpret_cast<const ulonglong2*>(src);
    unsigned long long sum2 = 0ull, sqa = 0ull, sqb = 0ull;
    unsigned long long dot2 = 0ull, ssq2 = 0ull, csq2 = 0ull;

    // i = 0 carries the prefix (float4 idx < 160 = chunks[n,:10,:]).
    {
        ulonglong2 v = __ldg(&cb[t]);
        add2(sum2, v.x); add2(sum2, v.y);
        fma2(sqa, v.x, v.x); fma2(sqb, v.y, v.y);
        if (t < 160) {
            ulonglong2 c = __ldg(reinterpret_cast<const ulonglong2*>(prev + 118 * 64) + t);
            fma2(dot2, v.x, c.x); fma2(dot2, v.y, c.y);
            fma2(ssq2, v.x, v.x); fma2(ssq2, v.y, v.y);
            fma2(csq2, c.x, c.x); fma2(csq2, c.y, c.y);
        }
    }
    #pragma unroll
    for (int i = 1; i < 4; i++) {
        ulonglong2 v = __ldg(&cb[t + 256 * i]);
        add2(sum2, v.x); add2(sum2, v.y);
        fma2(sqa, v.x, v.x); fma2(sqb, v.y, v.y);
    }

    // Wait for the TMA half (phase 0).
    {
        uint32_t done;
        asm volatile(
            "{\n\t.reg .pred p;\n\t"
            "mbarrier.try_wait.parity.acquire.cta.shared::cta.b64 p, [%1], 0;\n\t"
            "selp.b32 %0, 1, 0, p;\n\t}"
            : "=r"(done) : "r"(mbar_a) : "memory");
        if (!done) {
            asm volatile(
                "{\n\t.reg .pred P1;\n\t"
                "W_%=:\n\t"
                "mbarrier.try_wait.parity.acquire.cta.shared::cta.b64 P1, [%0], 0, 0x989680;\n\t"
                "@P1 bra.uni D_%=;\n\t"
                "bra.uni W_%=;\n\t"
                "D_%=:\n\t}"
                :: "r"(mbar_a) : "memory");
        }
    }

    // Consume SMEM half (1024 float4).
    const ulonglong2* t2 = reinterpret_cast<const ulonglong2*>(tile);
    #pragma unroll
    for (int i = 0; i < 4; i++) {
        ulonglong2 v = t2[t + 256 * i];
        add2(sum2, v.x); add2(sum2, v.y);
        fma2(sqa, v.x, v.x); fma2(sqb, v.y, v.y);
    }

    float sum = hsum2(sum2);
    float sq  = hsum2(sqa) + hsum2(sqb);
    float dot = hsum2(dot2);
    float ssq = hsum2(ssq2);
    float csq = hsum2(csq2);

    #pragma unroll
    for (int off = 16; off > 0; off >>= 1) {
        sum += __shfl_down_sync(0xffffffffu, sum, off);
        sq  += __shfl_down_sync(0xffffffffu, sq,  off);
        dot += __shfl_down_sync(0xffffffffu, dot, off);
        ssq += __shfl_down_sync(0xffffffffu, ssq, off);
        csq += __shfl_down_sync(0xffffffffu, csq, off);
    }

    const int wid = t >> 5, lid = t & 31;
    if (lid == 0) {
        red[wid][0] = sum; red[wid][1] = sq; red[wid][2] = dot;
        red[wid][3] = ssq; red[wid][4] = csq;
    }
    __syncthreads();

    if (t == 0) {
        float S = 0.f, Q = 0.f, D = 0.f, SS = 0.f, CS = 0.f;
        #pragma unroll
        for (int w = 0; w < 8; w++) {
            S += red[w][0]; Q += red[w][1]; D += red[w][2];
            SS += red[w][3]; CS += red[w][4];
        }
        const float M = 8192.0f;
        float var = (Q - S * S / M) / (M - 1.0f);
        float sd = sqrtf(fmaxf(var, 0.0f));

        float realism;
        if (sd < 0.01f)      realism = sd * 10.0f;
        else if (sd > 0.5f)  realism = 0.5f / sd;
        else                 realism = 1.0f - fabsf(sd - 0.1f);

        float denom = fmaxf(sqrtf(SS) * sqrtf(CS), 1e-8f);
        float boundary = D / denom;

        out[n] = realism + 0.3f * 0.5f + 0.2f * boundary;
    }
}

extern "C" void kernel_launch(void* const* d_in, const int* in_sizes, int n_in,
                              void* d_out, int out_size)
{
    const float* chunks = (const float*)d_in[0];   // [4096,128,64] f32
    // d_in[1] = regime_probs [9] — unused (constant 0.5 consistency)
    const float* prev = (const float*)d_in[2];     // [128,64] f32
    float* out = (float*)d_out;                    // [4096] f32

    const int n_chunks = in_sizes[0] / (128 * 64); // 4096
    chunk_ranker_kernel<<<n_chunks, 256>>>(chunks, prev, out);
}

// round 9
// speedup vs baseline: 1.0830x; 1.0230x over previous
#include <cuda_runtime.h>

// out[n] = realism(std(chunks[n])) + 0.3*0.5 + 0.2*cos(chunks[n,:10,:], prev[-10:,:])
//
// chunks: [4096, 128, 64] f32  -> 8192 floats per chunk = 2048 float4
// prev:   [128, 64] f32, ctx = last 10 rows = 640 floats (offset 7552, 16B aligned)
// out:    [4096] f32
//
// Final kernel (R2 architecture). The workload is a read-once 128MB stream;
// measured plateau across 7 architectures is ~5.4-5.8 TB/s, so the simple
// batched-LDG one-CTA-per-chunk form is at the effective memory ceiling.

__global__ __launch_bounds__(256) void chunk_ranker_kernel(
    const float4* __restrict__ chunks4,
    const float* __restrict__ prev,
    float* __restrict__ out)
{
    const int n = blockIdx.x;
    const int t = threadIdx.x;
    const float4* base = chunks4 + (size_t)n * 2048;
    const float4* ctx4 = reinterpret_cast<const float4*>(prev + 118 * 64); // 640 floats = 160 float4

    float sum = 0.f, sq = 0.f, dot = 0.f, ssq = 0.f, csq = 0.f;

    // Iteration i=0 covers float4 indices [0,256): only j<160 touches the prefix.
    {
        float4 v = base[t];
        sum += v.x + v.y + v.z + v.w;
        sq  += v.x*v.x + v.y*v.y + v.z*v.z + v.w*v.w;
        if (t < 160) {
            float4 c = __ldg(&ctx4[t]);
            dot += v.x*c.x + v.y*c.y + v.z*c.z + v.w*c.w;
            ssq += v.x*v.x + v.y*v.y + v.z*v.z + v.w*v.w;
            csq += c.x*c.x + c.y*c.y + c.z*c.z + c.w*c.w;
        }
    }
    #pragma unroll
    for (int i = 1; i < 8; i++) {
        float4 v = base[t + 256 * i];
        sum += v.x + v.y + v.z + v.w;
        sq  += v.x*v.x + v.y*v.y + v.z*v.z + v.w*v.w;
    }

    // Warp reduction of 5 quantities
    #pragma unroll
    for (int off = 16; off > 0; off >>= 1) {
        sum += __shfl_down_sync(0xffffffffu, sum, off);
        sq  += __shfl_down_sync(0xffffffffu, sq,  off);
        dot += __shfl_down_sync(0xffffffffu, dot, off);
        ssq += __shfl_down_sync(0xffffffffu, ssq, off);
        csq += __shfl_down_sync(0xffffffffu, csq, off);
    }

    __shared__ float red[8][5];
    const int wid = t >> 5, lid = t & 31;
    if (lid == 0) {
        red[wid][0] = sum; red[wid][1] = sq; red[wid][2] = dot;
        red[wid][3] = ssq; red[wid][4] = csq;
    }
    __syncthreads();

    if (t == 0) {
        float S = 0.f, Q = 0.f, D = 0.f, SS = 0.f, CS = 0.f;
        #pragma unroll
        for (int w = 0; w < 8; w++) {
            S += red[w][0]; Q += red[w][1]; D += red[w][2];
            SS += red[w][3]; CS += red[w][4];
        }
        const float M = 8192.0f;
        float var = (Q - S * S / M) / (M - 1.0f);
        float std = sqrtf(fmaxf(var, 0.0f));

        float realism;
        if (std < 0.01f)      realism = std * 10.0f;
        else if (std > 0.5f)  realism = 0.5f / std;
        else                  realism = 1.0f - fabsf(std - 0.1f);

        float denom = fmaxf(sqrtf(SS) * sqrtf(CS), 1e-8f);
        float boundary = D / denom;

        out[n] = realism + 0.3f * 0.5f + 0.2f * boundary;
    }
}

extern "C" void kernel_launch(void* const* d_in, const int* in_sizes, int n_in,
                              void* d_out, int out_size)
{
    const float4* chunks4 = (const float4*)d_in[0];   // [4096,128,64] f32
    // d_in[1] = regime_probs [9] — unused (constant consistency 0.5)
    const float* prev = (const float*)d_in[2];        // [128,64] f32
    float* out = (float*)d_out;                       // [4096] f32

    const int n_chunks = in_sizes[0] / (128 * 64);    // 4096
    chunk_ranker_kernel<<<n_chunks, 256>>>(chunks4, prev, out);
}